// round 1
// baseline (speedup 1.0000x reference)
#include <cuda_runtime.h>
#include <cstdint>
#include <math.h>

// ---------------------------------------------------------------------------
// Shapes
//   B=32, P=1024, HID=512, H=8, D=64, MEM=64, RANK=64
// Full algebraic reduction:
//   coeffs[b,p,q] = sum_{i<16} F[b,p,i]*Hh[b,q,i] + Hh[b,q,16]
// where F are 16 per-(b,p) features (alpha_h, beta_h per head) and
// Hh = G'(17x17) applied to [F,1].
// ---------------------------------------------------------------------------

#define Bx 32
#define Pn 1024
#define Hn 8
#define Dn 64

// scratch (allocation-free: __device__ globals)
__device__ float g_A[Hn * 64];        // A[h][m] = sum_d w_k[h*64+d]*w_mem[m*64+d]
__device__ float g_G[17 * 17];        // bilinear form
__device__ float g_S1[Bx * Hn];
__device__ float g_S2[Bx * Hn];
__device__ float g_xmm[Bx * 2];       // per-batch max/min of x
__device__ float g_F[(size_t)Bx * 16 * Pn];   // [b][i][p]
__device__ float g_Hh[(size_t)Bx * 17 * Pn];  // [b][i][p]

// ---------------------------------------------------------------------------
// Kernel P: tiny weight preprocessing (1 block)
// ---------------------------------------------------------------------------
__global__ void __launch_bounds__(512) kPrep(
    const float* __restrict__ w_k, const float* __restrict__ w_mem,
    const float* __restrict__ w_u, const float* __restrict__ b_u,
    const float* __restrict__ w_v2, const float* __restrict__ b_v2,
    const float* __restrict__ w_v, const float* __restrict__ b_v)
{
    __shared__ float sWU[64][17];
    __shared__ float sWV[64][17];
    int tid = threadIdx.x;

    // A[h][m]
    {
        int h = tid >> 6, m = tid & 63;
        float s = 0.f;
        #pragma unroll 8
        for (int d = 0; d < 64; d++)
            s = fmaf(w_k[h * 64 + d], w_mem[m * 64 + d], s);
        g_A[tid] = s;
    }

    // WU[r][i], WV[r][i] for i<16 (i<8 -> w_v factor, i>=8 -> b_v factor)
    for (int idx = tid; idx < 64 * 16; idx += 512) {
        int r = idx >> 4, i = idx & 15, h = i & 7;
        const float* col = (i < 8) ? w_v : b_v;
        float su = 0.f, sv = 0.f;
        #pragma unroll 8
        for (int d = 0; d < 64; d++) {
            float c = col[h * 64 + d];
            su = fmaf(w_u[r * 512 + h * 64 + d], c, su);
            sv = fmaf(w_v2[r * 512 + h * 64 + d], c, sv);
        }
        sWU[r][i] = su;
        sWV[r][i] = sv;
    }
    if (tid < 64) { sWU[tid][16] = b_u[tid]; sWV[tid][16] = b_v2[tid]; }
    __syncthreads();

    // G[i][j] = sum_r WU[r][i]*WV[r][j]
    for (int idx = tid; idx < 289; idx += 512) {
        int i = idx / 17, j = idx % 17;
        float s = 0.f;
        #pragma unroll 8
        for (int r = 0; r < 64; r++)
            s = fmaf(sWU[r][i], sWV[r][j], s);
        g_G[idx] = s;
    }
}

// ---------------------------------------------------------------------------
// Kernel X: per-batch max/min of x
// ---------------------------------------------------------------------------
__global__ void __launch_bounds__(256) kMinMax(const float* __restrict__ x)
{
    int b = blockIdx.x, tid = threadIdx.x;
    float mx = -INFINITY, mn = INFINITY;
    for (int p = tid; p < Pn; p += 256) {
        float v = x[b * Pn + p];
        mx = fmaxf(mx, v); mn = fminf(mn, v);
    }
    #pragma unroll
    for (int off = 16; off; off >>= 1) {
        mx = fmaxf(mx, __shfl_down_sync(0xffffffffu, mx, off));
        mn = fminf(mn, __shfl_down_sync(0xffffffffu, mn, off));
    }
    __shared__ float smx[8], smn[8];
    if ((tid & 31) == 0) { smx[tid >> 5] = mx; smn[tid >> 5] = mn; }
    __syncthreads();
    if (tid == 0) {
        float Mx = smx[0], Mn = smn[0];
        #pragma unroll
        for (int i = 1; i < 8; i++) { Mx = fmaxf(Mx, smx[i]); Mn = fminf(Mn, smn[i]); }
        g_xmm[b * 2 + 0] = Mx;
        g_xmm[b * 2 + 1] = Mn;
    }
}

// ---------------------------------------------------------------------------
// Kernel S: softmax statistics  S1[b,h]=sum_m T, S2[b,h]=sum_m T^2
//   T[m] = (sum_p x_p e^{a x_p - sh}) / (sum_p e^{a x_p - sh})
// grid (H, B), 512 threads; 8 threads per m.
// ---------------------------------------------------------------------------
__global__ void __launch_bounds__(512) kStats(const float* __restrict__ x)
{
    int h = blockIdx.x, b = blockIdx.y;
    __shared__ float sx[Pn];
    __shared__ float sT[64];
    int tid = threadIdx.x;
    sx[tid] = x[b * Pn + tid];
    sx[tid + 512] = x[b * Pn + tid + 512];
    __syncthreads();

    int m = tid >> 3, sub = tid & 7;
    float a = g_A[h * 64 + m];
    float sh = (a >= 0.f) ? a * g_xmm[b * 2 + 0] : a * g_xmm[b * 2 + 1];
    float num = 0.f, den = 0.f;
    #pragma unroll 4
    for (int p = sub; p < Pn; p += 8) {
        float xv = sx[p];
        float e = __expf(fmaf(a, xv, -sh));
        den += e;
        num = fmaf(xv, e, num);
    }
    #pragma unroll
    for (int off = 4; off; off >>= 1) {
        num += __shfl_down_sync(0xffffffffu, num, off, 8);
        den += __shfl_down_sync(0xffffffffu, den, off, 8);
    }
    if (sub == 0) sT[m] = num / den;
    __syncthreads();
    if (tid < 32) {
        float t0 = sT[tid], t1 = sT[tid + 32];
        float s1 = t0 + t1;
        float s2 = fmaf(t0, t0, t1 * t1);
        #pragma unroll
        for (int off = 16; off; off >>= 1) {
            s1 += __shfl_down_sync(0xffffffffu, s1, off);
            s2 += __shfl_down_sync(0xffffffffu, s2, off);
        }
        if (tid == 0) { g_S1[b * Hn + h] = s1; g_S2[b * Hn + h] = s2; }
    }
}

// ---------------------------------------------------------------------------
// Kernel F: features F[b, i<16, p] and Hh[b, i<17, p]
// grid (P/128, B), 128 threads; one thread per p.
// ---------------------------------------------------------------------------
__global__ void __launch_bounds__(128) kFeat(
    const float* __restrict__ x,
    const float* __restrict__ w_q, const float* __restrict__ b_q,
    const float* __restrict__ w_v, const float* __restrict__ b_v)
{
    __shared__ float swq[512], sbq[512], swv[512], sbv[512];
    __shared__ float sG[17 * 17];
    __shared__ float sS1[8], sS2[8];
    int b = blockIdx.y;
    int tid = threadIdx.x;
    for (int i = tid; i < 512; i += 128) {
        swq[i] = w_q[i]; sbq[i] = b_q[i];
        swv[i] = w_v[i]; sbv[i] = b_v[i];
    }
    for (int i = tid; i < 289; i += 128) sG[i] = g_G[i];
    if (tid < 8) { sS1[tid] = g_S1[b * Hn + tid]; sS2[tid] = g_S2[b * Hn + tid]; }
    __syncthreads();

    int p = blockIdx.x * 128 + tid;
    float xv = x[b * Pn + p];
    float f[17];
    #pragma unroll
    for (int h = 0; h < 8; h++) {
        float a1 = 0.f, a2 = 0.f;
        #pragma unroll 8
        for (int d = 0; d < 64; d++) {
            float v = fmaf(xv, swq[h * 64 + d], sbq[h * 64 + d]);
            float qf = (v > 0.f) ? (v + 1.f) : __expf(v);   // elu(v)+1
            a1 = fmaf(qf, swv[h * 64 + d], a1);
            a2 = fmaf(qf, sbv[h * 64 + d], a2);
        }
        float s1 = sS1[h], s2 = sS2[h];
        f[h]     = fmaf(a1, s2, a2 * s1);        // alpha
        f[8 + h] = fmaf(a1, s1, 64.f * a2);      // beta
    }
    f[16] = 1.f;

    size_t baseF = ((size_t)b * 16) * Pn + p;
    #pragma unroll
    for (int i = 0; i < 16; i++) g_F[baseF + (size_t)i * Pn] = f[i];

    size_t baseH = ((size_t)b * 17) * Pn + p;
    #pragma unroll
    for (int i = 0; i < 17; i++) {
        float s = 0.f;
        #pragma unroll
        for (int j = 0; j < 17; j++) s = fmaf(sG[i * 17 + j], f[j], s);
        g_Hh[baseH + (size_t)i * Pn] = s;
    }
}

// ---------------------------------------------------------------------------
// Kernel G: main bilinear GEMM  out[b,p,q] = sum_{i<16} F[p,i]*Hh[q,i] + Hh[q,16]
// K=16 GEMM with packed fma.rn.f32x2 (FFMA2) for 2x fp32 rate.
// Block: 128x128 tile, 256 threads, 8x8 microtile split 4+4 for bank-conflict-free LDS.128.
// ---------------------------------------------------------------------------
#define PACK_SPLAT(out64, fa) \
    asm("mov.b64 %0, {%1, %1};" : "=l"(out64) : "r"(__float_as_uint(fa)))
#define PACK2(out64, lo, hi) \
    asm("mov.b64 %0, {%1, %2};" : "=l"(out64) : "r"(__float_as_uint(lo)), "r"(__float_as_uint(hi)))
#define FMA2(acc64, a64, b64) \
    asm("fma.rn.f32x2 %0, %1, %2, %0;" : "+l"(acc64) : "l"(a64), "l"(b64))
#define UNPACK2(lo, hi, in64) do { \
    unsigned _u0, _u1; \
    asm("mov.b64 {%0, %1}, %2;" : "=r"(_u0), "=r"(_u1) : "l"(in64)); \
    lo = __uint_as_float(_u0); hi = __uint_as_float(_u1); } while (0)

__global__ void __launch_bounds__(256) kGemm(float* __restrict__ out)
{
    const int b = blockIdx.z;
    const int tq0 = blockIdx.x * 128;
    const int tp0 = blockIdx.y * 128;

    __shared__ float sA[16][128];   // F tile   (rows = k, cols = p)
    __shared__ float sB[16][128];   // Hh tile  (rows = k, cols = q)
    __shared__ float sH16[128];     // Hh row 16 (bias per q)

    const int tid = threadIdx.x;
    const float* Fb = g_F + ((size_t)b * 16) * Pn;
    const float* Hb = g_Hh + ((size_t)b * 17) * Pn;

    #pragma unroll
    for (int rep = 0; rep < 2; rep++) {
        int idx = tid + rep * 256;       // 512 float4 per operand
        int row = idx >> 5, c4 = (idx & 31) << 2;
        *(float4*)&sA[row][c4] = *(const float4*)&Fb[(size_t)row * Pn + tp0 + c4];
        *(float4*)&sB[row][c4] = *(const float4*)&Hb[(size_t)row * Pn + tq0 + c4];
    }
    if (tid < 32)
        *(float4*)&sH16[tid * 4] = *(const float4*)&Hb[(size_t)16 * Pn + tq0 + tid * 4];
    __syncthreads();

    const int tx = tid & 15, ty = tid >> 4;
    const int r0 = ty * 4;               // rows r0..r0+3 and r0+64..r0+67
    const int c0 = tx * 4;               // cols c0..c0+3 and c0+64..c0+67

    unsigned long long acc[8][4];        // [row 0..7][col-pair 0..3]
    {
        float4 hA = *(const float4*)&sH16[c0];
        float4 hB = *(const float4*)&sH16[c0 + 64];
        unsigned long long h0, h1, h2, h3;
        PACK2(h0, hA.x, hA.y); PACK2(h1, hA.z, hA.w);
        PACK2(h2, hB.x, hB.y); PACK2(h3, hB.z, hB.w);
        #pragma unroll
        for (int r = 0; r < 8; r++) {
            acc[r][0] = h0; acc[r][1] = h1; acc[r][2] = h2; acc[r][3] = h3;
        }
    }

    #pragma unroll
    for (int k = 0; k < 16; k++) {
        float4 aA = *(const float4*)&sA[k][r0];
        float4 aB = *(const float4*)&sA[k][r0 + 64];
        float4 bA = *(const float4*)&sB[k][c0];
        float4 bB = *(const float4*)&sB[k][c0 + 64];
        unsigned long long b0, b1, b2, b3;
        PACK2(b0, bA.x, bA.y); PACK2(b1, bA.z, bA.w);
        PACK2(b2, bB.x, bB.y); PACK2(b3, bB.z, bB.w);
        float ar[8] = {aA.x, aA.y, aA.z, aA.w, aB.x, aB.y, aB.z, aB.w};
        #pragma unroll
        for (int r = 0; r < 8; r++) {
            unsigned long long ap;
            PACK_SPLAT(ap, ar[r]);
            FMA2(acc[r][0], ap, b0);
            FMA2(acc[r][1], ap, b1);
            FMA2(acc[r][2], ap, b2);
            FMA2(acc[r][3], ap, b3);
        }
    }

    float* outb = out + (size_t)b * Pn * Pn;
    #pragma unroll
    for (int r = 0; r < 8; r++) {
        int p = tp0 + ((r < 4) ? (r0 + r) : (r0 + 60 + r));  // r>=4 -> r0+64+(r-4)
        float4 v0, v1;
        UNPACK2(v0.x, v0.y, acc[r][0]);
        UNPACK2(v0.z, v0.w, acc[r][1]);
        UNPACK2(v1.x, v1.y, acc[r][2]);
        UNPACK2(v1.z, v1.w, acc[r][3]);
        float* rowp = outb + (size_t)p * Pn + tq0;
        *(float4*)&rowp[c0] = v0;
        *(float4*)&rowp[c0 + 64] = v1;
    }
}

// ---------------------------------------------------------------------------
// launch
// inputs: 0 x, 1 w_q, 2 b_q, 3 w_k, 4 b_k(unused), 5 w_v, 6 b_v, 7 w_mem,
//         8 w_u, 9 b_u, 10 w_v2, 11 b_v2
// ---------------------------------------------------------------------------
extern "C" void kernel_launch(void* const* d_in, const int* in_sizes, int n_in,
                              void* d_out, int out_size)
{
    const float* x    = (const float*)d_in[0];
    const float* w_q  = (const float*)d_in[1];
    const float* b_q  = (const float*)d_in[2];
    const float* w_k  = (const float*)d_in[3];
    const float* w_v  = (const float*)d_in[5];
    const float* b_v  = (const float*)d_in[6];
    const float* w_mem = (const float*)d_in[7];
    const float* w_u  = (const float*)d_in[8];
    const float* b_u  = (const float*)d_in[9];
    const float* w_v2 = (const float*)d_in[10];
    const float* b_v2 = (const float*)d_in[11];
    float* out = (float*)d_out;

    kPrep<<<1, 512>>>(w_k, w_mem, w_u, b_u, w_v2, b_v2, w_v, b_v);
    kMinMax<<<Bx, 256>>>(x);
    kStats<<<dim3(Hn, Bx), 512>>>(x);
    kFeat<<<dim3(Pn / 128, Bx), 128>>>(x, w_q, b_q, w_v, b_v);
    kGemm<<<dim3(Pn / 128, Pn / 128, Bx), 256>>>(out);
}